// round 1
// baseline (speedup 1.0000x reference)
#include <cuda_runtime.h>

#define H  1024
#define NH 16
#define HD 64
#define BB 2
#define SS 2048
#define T  (BB * SS)      // 4096 rows
#define K3 (3 * H)        // 3072

// ---- scratch (allocation-free rule: device globals) ----
__device__ float g_xn[(size_t)T * H];                       // 16 MB
__device__ float g_qkv[(size_t)3 * BB * NH * SS * HD];      // 48 MB, layout [3][B][NH][S][HD]
__device__ float g_ctx[(size_t)T * H];                      // 16 MB

// ============================================================
// LayerNorm: one block per row, 256 threads, float4
// ============================================================
__global__ __launch_bounds__(256) void ln_kernel(const float* __restrict__ x,
                                                 const float* __restrict__ gamma,
                                                 const float* __restrict__ beta) {
    int row = blockIdx.x;
    int tid = threadIdx.x;
    const float4* xr = (const float4*)(x + (size_t)row * H);
    float4 v = xr[tid];
    float s  = v.x + v.y + v.z + v.w;
    float ss = v.x * v.x + v.y * v.y + v.z * v.z + v.w * v.w;
#pragma unroll
    for (int off = 16; off > 0; off >>= 1) {
        s  += __shfl_xor_sync(0xffffffffu, s, off);
        ss += __shfl_xor_sync(0xffffffffu, ss, off);
    }
    __shared__ float red[16];
    int warp = tid >> 5, lane = tid & 31;
    if (lane == 0) { red[warp] = s; red[8 + warp] = ss; }
    __syncthreads();
    float ts = 0.f, tss = 0.f;
#pragma unroll
    for (int w = 0; w < 8; w++) { ts += red[w]; tss += red[8 + w]; }
    float mu   = ts * (1.0f / H);
    float var  = tss * (1.0f / H) - mu * mu;
    float rstd = rsqrtf(var + 1e-5f);
    float4 g  = ((const float4*)gamma)[tid];
    float4 bt = ((const float4*)beta)[tid];
    float4 o;
    o.x = (v.x - mu) * rstd * g.x + bt.x;
    o.y = (v.y - mu) * rstd * g.y + bt.y;
    o.z = (v.z - mu) * rstd * g.z + bt.z;
    o.w = (v.w - mu) * rstd * g.w + bt.w;
    ((float4*)(g_xn + (size_t)row * H))[tid] = o;
}

// ============================================================
// QKV GEMM: C[t,o] = sum_k g_xn[t,k] * Wqkv[o,k] + b[o]
// epilogue remaps to g_qkv[3][B][NH][S][HD]
// 128x128 tile, BK=16, 256 threads, 8x8 micro (4+4 split)
// ============================================================
__global__ __launch_bounds__(256) void qkv_gemm(const float* __restrict__ Wq,
                                                const float* __restrict__ bias) {
    const int K = H;
    __shared__ float As[16][128];
    __shared__ float Bs[16][128];
    int tid = threadIdx.x;
    int tx = tid & 15, ty = tid >> 4;
    int m0 = blockIdx.y * 128;
    int n0 = blockIdx.x * 128;
    const float* Aptr = g_xn + (size_t)m0 * K;
    const float* Bptr = Wq + (size_t)n0 * K;

    float acc[8][8];
#pragma unroll
    for (int i = 0; i < 8; i++)
#pragma unroll
        for (int j = 0; j < 8; j++) acc[i][j] = 0.f;

    for (int k0 = 0; k0 < K; k0 += 16) {
#pragma unroll
        for (int i = 0; i < 2; i++) {
            int f = tid + i * 256;
            int row = f >> 2;
            int kc = (f & 3) << 2;
            float4 a = *(const float4*)(Aptr + (size_t)row * K + k0 + kc);
            As[kc + 0][row] = a.x; As[kc + 1][row] = a.y;
            As[kc + 2][row] = a.z; As[kc + 3][row] = a.w;
            float4 b = *(const float4*)(Bptr + (size_t)row * K + k0 + kc);
            Bs[kc + 0][row] = b.x; Bs[kc + 1][row] = b.y;
            Bs[kc + 2][row] = b.z; Bs[kc + 3][row] = b.w;
        }
        __syncthreads();
#pragma unroll
        for (int k = 0; k < 16; k++) {
            float4 a0 = *(const float4*)&As[k][ty * 4];
            float4 a1 = *(const float4*)&As[k][64 + ty * 4];
            float4 b0 = *(const float4*)&Bs[k][tx * 4];
            float4 b1 = *(const float4*)&Bs[k][64 + tx * 4];
            float av[8] = {a0.x, a0.y, a0.z, a0.w, a1.x, a1.y, a1.z, a1.w};
            float bv[8] = {b0.x, b0.y, b0.z, b0.w, b1.x, b1.y, b1.z, b1.w};
#pragma unroll
            for (int i = 0; i < 8; i++)
#pragma unroll
                for (int j = 0; j < 8; j++)
                    acc[i][j] = fmaf(av[i], bv[j], acc[i][j]);
        }
        __syncthreads();
    }

#pragma unroll
    for (int i = 0; i < 8; i++) {
        int m = m0 + ((i < 4) ? ty * 4 + i : 64 + ty * 4 + (i - 4));
        int bb = m >> 11;
        int sIdx = m & 2047;
#pragma unroll
        for (int jg = 0; jg < 2; jg++) {
            int n = n0 + jg * 64 + tx * 4;
            int c = n >> 10;
            int rem = n & 1023;
            int hh = rem >> 6;
            int d = rem & 63;
            float4 r;
            r.x = acc[i][jg * 4 + 0] + bias[n + 0];
            r.y = acc[i][jg * 4 + 1] + bias[n + 1];
            r.z = acc[i][jg * 4 + 2] + bias[n + 2];
            r.w = acc[i][jg * 4 + 3] + bias[n + 3];
            float* dst = g_qkv + ((((size_t)(c * 2 + bb) * NH + hh) * SS + sIdx) * HD + d);
            *(float4*)dst = r;
        }
    }
}

// ============================================================
// Fused flash attention: one block per (bh, q-tile of 128)
// smem: Qs[64][128] Ks[64][128] Vs[128][64] Ps[128][136]
// ============================================================
#define PSTRIDE 136
#define ATTN_SMEM ((64 * 128 + 64 * 128 + 128 * 64 + 128 * PSTRIDE) * 4)

__global__ __launch_bounds__(256) void attn_kernel() {
    extern __shared__ float sm[];
    float* Qs = sm;                  // [64][128]  d-major
    float* Ks = Qs + 64 * 128;       // [64][128]  d-major
    float* Vs = Ks + 64 * 128;       // [128][64]  n-major
    float* Ps = Vs + 128 * 64;       // [128][136] m-major, padded

    int tid = threadIdx.x;
    int tx = tid & 15, ty = tid >> 4;
    int bh = blockIdx.y;             // b*16 + h
    int m0 = blockIdx.x * 128;

    const float* qp = g_qkv + (size_t)(0 + bh) * (SS * HD);
    const float* kp = g_qkv + (size_t)(32 + bh) * (SS * HD);
    const float* vp = g_qkv + (size_t)(64 + bh) * (SS * HD);

    // load Q tile, transposed into Qs[d][m]
#pragma unroll
    for (int i = 0; i < 8; i++) {
        int f = tid + i * 256;
        int row = f >> 4;
        int d4 = (f & 15) << 2;
        float4 v = *(const float4*)(qp + (size_t)(m0 + row) * HD + d4);
        Qs[(d4 + 0) * 128 + row] = v.x;
        Qs[(d4 + 1) * 128 + row] = v.y;
        Qs[(d4 + 2) * 128 + row] = v.z;
        Qs[(d4 + 3) * 128 + row] = v.w;
    }

    int mloc[8];
#pragma unroll
    for (int i = 0; i < 8; i++) mloc[i] = (i < 4) ? ty * 4 + i : 64 + ty * 4 + (i - 4);

    float m_i[8], l_i[8], o[8][4];
#pragma unroll
    for (int i = 0; i < 8; i++) {
        m_i[i] = -1e30f;
        l_i[i] = 0.f;
        o[i][0] = o[i][1] = o[i][2] = o[i][3] = 0.f;
    }

    for (int n0 = 0; n0 < SS; n0 += 128) {
        __syncthreads();   // previous P*V done reading Vs/Ps
#pragma unroll
        for (int i = 0; i < 8; i++) {
            int f = tid + i * 256;
            int row = f >> 4;
            int d4 = (f & 15) << 2;
            float4 kv = *(const float4*)(kp + (size_t)(n0 + row) * HD + d4);
            Ks[(d4 + 0) * 128 + row] = kv.x;
            Ks[(d4 + 1) * 128 + row] = kv.y;
            Ks[(d4 + 2) * 128 + row] = kv.z;
            Ks[(d4 + 3) * 128 + row] = kv.w;
            float4 vv4 = *(const float4*)(vp + (size_t)(n0 + row) * HD + d4);
            *(float4*)&Vs[row * 64 + d4] = vv4;
        }
        __syncthreads();

        // S = Q K^T (128x128, K=64)
        float sc[8][8];
#pragma unroll
        for (int i = 0; i < 8; i++)
#pragma unroll
            for (int j = 0; j < 8; j++) sc[i][j] = 0.f;
#pragma unroll
        for (int d = 0; d < 64; d++) {
            float4 a0 = *(const float4*)&Qs[d * 128 + ty * 4];
            float4 a1 = *(const float4*)&Qs[d * 128 + 64 + ty * 4];
            float4 b0 = *(const float4*)&Ks[d * 128 + tx * 4];
            float4 b1 = *(const float4*)&Ks[d * 128 + 64 + tx * 4];
            float av[8] = {a0.x, a0.y, a0.z, a0.w, a1.x, a1.y, a1.z, a1.w};
            float bv[8] = {b0.x, b0.y, b0.z, b0.w, b1.x, b1.y, b1.z, b1.w};
#pragma unroll
            for (int i = 0; i < 8; i++)
#pragma unroll
                for (int j = 0; j < 8; j++)
                    sc[i][j] = fmaf(av[i], bv[j], sc[i][j]);
        }

        // online softmax (row stats across 16-lane groups)
#pragma unroll
        for (int i = 0; i < 8; i++) {
            float rm = -1e30f;
#pragma unroll
            for (int j = 0; j < 8; j++) {
                sc[i][j] *= 0.125f;   // 1/sqrt(64)
                rm = fmaxf(rm, sc[i][j]);
            }
            rm = fmaxf(rm, __shfl_xor_sync(0xffffffffu, rm, 1));
            rm = fmaxf(rm, __shfl_xor_sync(0xffffffffu, rm, 2));
            rm = fmaxf(rm, __shfl_xor_sync(0xffffffffu, rm, 4));
            rm = fmaxf(rm, __shfl_xor_sync(0xffffffffu, rm, 8));
            float nm = fmaxf(m_i[i], rm);
            float alpha = __expf(m_i[i] - nm);
            m_i[i] = nm;
            float rs = 0.f;
#pragma unroll
            for (int j = 0; j < 8; j++) {
                float p = __expf(sc[i][j] - nm);
                sc[i][j] = p;
                rs += p;
            }
            rs += __shfl_xor_sync(0xffffffffu, rs, 1);
            rs += __shfl_xor_sync(0xffffffffu, rs, 2);
            rs += __shfl_xor_sync(0xffffffffu, rs, 4);
            rs += __shfl_xor_sync(0xffffffffu, rs, 8);
            l_i[i] = l_i[i] * alpha + rs;
            o[i][0] *= alpha; o[i][1] *= alpha; o[i][2] *= alpha; o[i][3] *= alpha;
            *(float4*)&Ps[mloc[i] * PSTRIDE + tx * 4] =
                make_float4(sc[i][0], sc[i][1], sc[i][2], sc[i][3]);
            *(float4*)&Ps[mloc[i] * PSTRIDE + 64 + tx * 4] =
                make_float4(sc[i][4], sc[i][5], sc[i][6], sc[i][7]);
        }
        __syncthreads();

        // O += P * V (128x64, K=128)
#pragma unroll 4
        for (int n = 0; n < 128; n += 4) {
            float4 v0 = *(const float4*)&Vs[(n + 0) * 64 + tx * 4];
            float4 v1 = *(const float4*)&Vs[(n + 1) * 64 + tx * 4];
            float4 v2 = *(const float4*)&Vs[(n + 2) * 64 + tx * 4];
            float4 v3 = *(const float4*)&Vs[(n + 3) * 64 + tx * 4];
#pragma unroll
            for (int i = 0; i < 8; i++) {
                float4 p = *(const float4*)&Ps[mloc[i] * PSTRIDE + n];
                o[i][0] = fmaf(p.x, v0.x, o[i][0]);
                o[i][1] = fmaf(p.x, v0.y, o[i][1]);
                o[i][2] = fmaf(p.x, v0.z, o[i][2]);
                o[i][3] = fmaf(p.x, v0.w, o[i][3]);
                o[i][0] = fmaf(p.y, v1.x, o[i][0]);
                o[i][1] = fmaf(p.y, v1.y, o[i][1]);
                o[i][2] = fmaf(p.y, v1.z, o[i][2]);
                o[i][3] = fmaf(p.y, v1.w, o[i][3]);
                o[i][0] = fmaf(p.z, v2.x, o[i][0]);
                o[i][1] = fmaf(p.z, v2.y, o[i][1]);
                o[i][2] = fmaf(p.z, v2.z, o[i][2]);
                o[i][3] = fmaf(p.z, v2.w, o[i][3]);
                o[i][0] = fmaf(p.w, v3.x, o[i][0]);
                o[i][1] = fmaf(p.w, v3.y, o[i][1]);
                o[i][2] = fmaf(p.w, v3.z, o[i][2]);
                o[i][3] = fmaf(p.w, v3.w, o[i][3]);
            }
        }
    }

    // finalize: ctx[t, h*64 + d]
    int b = bh >> 4, h = bh & 15;
#pragma unroll
    for (int i = 0; i < 8; i++) {
        float inv = 1.0f / l_i[i];
        int t = b * SS + m0 + mloc[i];
        float4 r = make_float4(o[i][0] * inv, o[i][1] * inv, o[i][2] * inv, o[i][3] * inv);
        *(float4*)(g_ctx + (size_t)t * H + h * 64 + tx * 4) = r;
    }
}

// ============================================================
// Output GEMM + bias + residual: out[t,o] = resid + b[o] + ctx*Wout^T
// ============================================================
__global__ __launch_bounds__(256) void out_gemm(const float* __restrict__ Wo,
                                                const float* __restrict__ bias,
                                                const float* __restrict__ resid,
                                                float* __restrict__ out) {
    const int K = H;
    __shared__ float As[16][128];
    __shared__ float Bs[16][128];
    int tid = threadIdx.x;
    int tx = tid & 15, ty = tid >> 4;
    int m0 = blockIdx.y * 128;
    int n0 = blockIdx.x * 128;
    const float* Aptr = g_ctx + (size_t)m0 * K;
    const float* Bptr = Wo + (size_t)n0 * K;

    float acc[8][8];
#pragma unroll
    for (int i = 0; i < 8; i++)
#pragma unroll
        for (int j = 0; j < 8; j++) acc[i][j] = 0.f;

    for (int k0 = 0; k0 < K; k0 += 16) {
#pragma unroll
        for (int i = 0; i < 2; i++) {
            int f = tid + i * 256;
            int row = f >> 2;
            int kc = (f & 3) << 2;
            float4 a = *(const float4*)(Aptr + (size_t)row * K + k0 + kc);
            As[kc + 0][row] = a.x; As[kc + 1][row] = a.y;
            As[kc + 2][row] = a.z; As[kc + 3][row] = a.w;
            float4 b = *(const float4*)(Bptr + (size_t)row * K + k0 + kc);
            Bs[kc + 0][row] = b.x; Bs[kc + 1][row] = b.y;
            Bs[kc + 2][row] = b.z; Bs[kc + 3][row] = b.w;
        }
        __syncthreads();
#pragma unroll
        for (int k = 0; k < 16; k++) {
            float4 a0 = *(const float4*)&As[k][ty * 4];
            float4 a1 = *(const float4*)&As[k][64 + ty * 4];
            float4 b0 = *(const float4*)&Bs[k][tx * 4];
            float4 b1 = *(const float4*)&Bs[k][64 + tx * 4];
            float av[8] = {a0.x, a0.y, a0.z, a0.w, a1.x, a1.y, a1.z, a1.w};
            float bv[8] = {b0.x, b0.y, b0.z, b0.w, b1.x, b1.y, b1.z, b1.w};
#pragma unroll
            for (int i = 0; i < 8; i++)
#pragma unroll
                for (int j = 0; j < 8; j++)
                    acc[i][j] = fmaf(av[i], bv[j], acc[i][j]);
        }
        __syncthreads();
    }

#pragma unroll
    for (int i = 0; i < 8; i++) {
        int m = m0 + ((i < 4) ? ty * 4 + i : 64 + ty * 4 + (i - 4));
#pragma unroll
        for (int jg = 0; jg < 2; jg++) {
            int n = n0 + jg * 64 + tx * 4;
            size_t idx = (size_t)m * H + n;
            float4 hv = *(const float4*)(resid + idx);
            float4 r;
            r.x = acc[i][jg * 4 + 0] + bias[n + 0] + hv.x;
            r.y = acc[i][jg * 4 + 1] + bias[n + 1] + hv.y;
            r.z = acc[i][jg * 4 + 2] + bias[n + 2] + hv.z;
            r.w = acc[i][jg * 4 + 3] + bias[n + 3] + hv.w;
            *(float4*)(out + idx) = r;
        }
    }
}

// ============================================================
extern "C" void kernel_launch(void* const* d_in, const int* in_sizes, int n_in,
                              void* d_out, int out_size) {
    const float* hidden = (const float*)d_in[0];
    const float* gamma  = (const float*)d_in[1];
    const float* beta   = (const float*)d_in[2];
    const float* Wqkv   = (const float*)d_in[3];
    const float* bqkv   = (const float*)d_in[4];
    const float* Wout   = (const float*)d_in[5];
    const float* bout   = (const float*)d_in[6];
    float* out = (float*)d_out;

    ln_kernel<<<T, 256>>>(hidden, gamma, beta);

    dim3 g1(K3 / 128, T / 128);
    qkv_gemm<<<g1, 256>>>(Wqkv, bqkv);

    cudaFuncSetAttribute(attn_kernel, cudaFuncAttributeMaxDynamicSharedMemorySize, ATTN_SMEM);
    attn_kernel<<<dim3(SS / 128, BB * NH), 256, ATTN_SMEM>>>();

    dim3 g2(H / 128, T / 128);
    out_gemm<<<g2, 256>>>(Wout, bout, hidden, out);
}

// round 4
// speedup vs baseline: 2.9051x; 2.9051x over previous
#include <cuda_runtime.h>
#include <cstdint>

#define H  1024
#define NH 16
#define HD 64
#define BB 2
#define SS 2048
#define T  (BB * SS)      // 4096 rows
#define K3 (3 * H)        // 3072

// ---- scratch (allocation-free rule: device globals) ----
// NOTE: these are referenced ONLY from device code. Passing them as host-side
// kernel args gives the host shadow address (readable via ATS on GB300 -> zeros).
__device__ float g_xn[(size_t)T * H];                       // 16 MB
__device__ float g_qkv[(size_t)3 * BB * NH * SS * HD];      // 48 MB, [3][B][NH][S][HD]
__device__ float g_ctx[(size_t)T * H];                      // 16 MB

// ============================================================
// helpers: tf32 convert + mma.m16n8k8 tf32
// ============================================================
__device__ __forceinline__ uint32_t f2tf(float f) {
    uint32_t u;
    asm("cvt.rna.tf32.f32 %0, %1;" : "=r"(u) : "f"(f));
    return u;
}

__device__ __forceinline__ void mma_tf32(float4& c, const uint32_t a[4], const uint32_t b[2]) {
    asm volatile(
        "mma.sync.aligned.m16n8k8.row.col.f32.tf32.tf32.f32 "
        "{%0,%1,%2,%3}, {%4,%5,%6,%7}, {%8,%9}, {%0,%1,%2,%3};"
        : "+f"(c.x), "+f"(c.y), "+f"(c.z), "+f"(c.w)
        : "r"(a[0]), "r"(a[1]), "r"(a[2]), "r"(a[3]), "r"(b[0]), "r"(b[1]));
}

// ============================================================
// LayerNorm: one block per row, 256 threads, float4
// ============================================================
__global__ __launch_bounds__(256) void ln_kernel(const float* __restrict__ x,
                                                 const float* __restrict__ gamma,
                                                 const float* __restrict__ beta) {
    int row = blockIdx.x;
    int tid = threadIdx.x;
    const float4* xr = (const float4*)(x + (size_t)row * H);
    float4 v = xr[tid];
    float s  = v.x + v.y + v.z + v.w;
    float ss = v.x * v.x + v.y * v.y + v.z * v.z + v.w * v.w;
#pragma unroll
    for (int off = 16; off > 0; off >>= 1) {
        s  += __shfl_xor_sync(0xffffffffu, s, off);
        ss += __shfl_xor_sync(0xffffffffu, ss, off);
    }
    __shared__ float red[16];
    int warp = tid >> 5, lane = tid & 31;
    if (lane == 0) { red[warp] = s; red[8 + warp] = ss; }
    __syncthreads();
    float ts = 0.f, tss = 0.f;
#pragma unroll
    for (int w = 0; w < 8; w++) { ts += red[w]; tss += red[8 + w]; }
    float mu   = ts * (1.0f / H);
    float var  = tss * (1.0f / H) - mu * mu;
    float rstd = rsqrtf(var + 1e-5f);
    float4 g  = ((const float4*)gamma)[tid];
    float4 bt = ((const float4*)beta)[tid];
    float4 o;
    o.x = (v.x - mu) * rstd * g.x + bt.x;
    o.y = (v.y - mu) * rstd * g.y + bt.y;
    o.z = (v.z - mu) * rstd * g.z + bt.z;
    o.w = (v.w - mu) * rstd * g.w + bt.w;
    ((float4*)(g_xn + (size_t)row * H))[tid] = o;
}

// ============================================================
// TF32 tensor-core GEMM: 128x128 tile, BK=32, 256 threads (8 warps, 2x4)
// A source selected DEVICE-SIDE by MODE (g_xn or g_ctx).
// MODE 0: qkv epilogue (bias + remap to [3][B][NH][S][HD])
// MODE 1: out epilogue (bias + residual -> out)
// ============================================================
#define SGA 36

template <int MODE>
__global__ __launch_bounds__(256, 2) void gemm_tf32(const float* __restrict__ Bg,
                                                    const float* __restrict__ bias,
                                                    const float* __restrict__ resid,
                                                    float* __restrict__ outp) {
    __shared__ uint32_t As[128 * SGA];
    __shared__ uint32_t Bs[128 * SGA];
    const float* Ag = (MODE == 0) ? g_xn : g_ctx;   // device-side symbol resolution
    const int Kdim = H;
    int tid = threadIdx.x;
    int lane = tid & 31;
    int warp = tid >> 5;
    int wm = warp >> 2;        // 0..1
    int wn = warp & 3;         // 0..3
    int g = lane >> 2;         // 0..7
    int t = lane & 3;          // 0..3
    int m0 = blockIdx.y * 128;
    int n0 = blockIdx.x * 128;

    float4 acc[4][4];
#pragma unroll
    for (int i = 0; i < 4; i++)
#pragma unroll
        for (int j = 0; j < 4; j++) acc[i][j] = make_float4(0.f, 0.f, 0.f, 0.f);

    int srow = tid >> 3;
    int sc4  = (tid & 7) * 4;

    for (int k0 = 0; k0 < Kdim; k0 += 32) {
#pragma unroll
        for (int i = 0; i < 4; i++) {
            int row = srow + i * 32;
            float4 a = *(const float4*)(Ag + (size_t)(m0 + row) * Kdim + k0 + sc4);
            uint4 ua = make_uint4(f2tf(a.x), f2tf(a.y), f2tf(a.z), f2tf(a.w));
            *(uint4*)&As[row * SGA + sc4] = ua;
            float4 b = *(const float4*)(Bg + (size_t)(n0 + row) * Kdim + k0 + sc4);
            uint4 ub = make_uint4(f2tf(b.x), f2tf(b.y), f2tf(b.z), f2tf(b.w));
            *(uint4*)&Bs[row * SGA + sc4] = ub;
        }
        __syncthreads();

#pragma unroll
        for (int kk = 0; kk < 32; kk += 8) {
            uint32_t af[4][4], bf[4][2];
#pragma unroll
            for (int im = 0; im < 4; im++) {
                int r0 = wm * 64 + im * 16 + g;
                af[im][0] = As[r0 * SGA + kk + t];
                af[im][1] = As[(r0 + 8) * SGA + kk + t];
                af[im][2] = As[r0 * SGA + kk + t + 4];
                af[im][3] = As[(r0 + 8) * SGA + kk + t + 4];
            }
#pragma unroll
            for (int jn = 0; jn < 4; jn++) {
                int nr = wn * 32 + jn * 8 + g;
                bf[jn][0] = Bs[nr * SGA + kk + t];
                bf[jn][1] = Bs[nr * SGA + kk + t + 4];
            }
#pragma unroll
            for (int im = 0; im < 4; im++)
#pragma unroll
                for (int jn = 0; jn < 4; jn++)
                    mma_tf32(acc[im][jn], af[im], bf[jn]);
        }
        __syncthreads();
    }

    // epilogue
#pragma unroll
    for (int im = 0; im < 4; im++) {
        int rlo = m0 + wm * 64 + im * 16 + g;
        int rhi = rlo + 8;
#pragma unroll
        for (int jn = 0; jn < 4; jn++) {
            int n = n0 + wn * 32 + jn * 8 + 2 * t;
            float b0 = bias[n], b1 = bias[n + 1];
            if (MODE == 0) {
                int c = n >> 10;
                int rem = n & 1023;
                int hh = rem >> 6;
                int d = rem & 63;
#pragma unroll
                for (int h = 0; h < 2; h++) {
                    int m = h ? rhi : rlo;
                    int bb = m >> 11;
                    int sIdx = m & 2047;
                    float2 r;
                    r.x = (h ? acc[im][jn].z : acc[im][jn].x) + b0;
                    r.y = (h ? acc[im][jn].w : acc[im][jn].y) + b1;
                    float* dst = g_qkv + ((((size_t)(c * 2 + bb) * NH + hh) * SS + sIdx) * HD + d);
                    *(float2*)dst = r;
                }
            } else {
#pragma unroll
                for (int h = 0; h < 2; h++) {
                    int m = h ? rhi : rlo;
                    size_t idx = (size_t)m * H + n;
                    float2 hv = *(const float2*)(resid + idx);
                    float2 r;
                    r.x = (h ? acc[im][jn].z : acc[im][jn].x) + b0 + hv.x;
                    r.y = (h ? acc[im][jn].w : acc[im][jn].y) + b1 + hv.y;
                    *(float2*)(outp + idx) = r;
                }
            }
        }
    }
}

// ============================================================
// Flash attention, tf32 mma, ROW-COMPLETE warp tiling:
// warp w owns q-rows [w*16, w*16+16) and the FULL n/d extent,
// so softmax row stats are warp-local (shfl over t lanes only).
// smem (tf32 bits): Qs[128][68], KP[128][132] (K then P), Vs[128][72]
// ============================================================
#define SQ 68
#define SKP 132
#define SV 72
#define Q_OFF 0
#define KP_OFF (128 * SQ)
#define V_OFF (KP_OFF + 128 * SKP)
#define ATTN_SMEM_WORDS (V_OFF + 128 * SV)
#define ATTN_SMEM_BYTES (ATTN_SMEM_WORDS * 4)

__global__ __launch_bounds__(256, 1) void attn_kernel() {
    extern __shared__ uint32_t sm[];
    uint32_t* Qs = sm + Q_OFF;
    uint32_t* KP = sm + KP_OFF;
    uint32_t* Vs = sm + V_OFF;

    int tid = threadIdx.x;
    int lane = tid & 31;
    int warp = tid >> 5;     // 0..7, owns rows warp*16..+15
    int g = lane >> 2;       // 0..7
    int t = lane & 3;        // 0..3
    int bh = blockIdx.y;
    int m0 = blockIdx.x * 128;

    const float* qp = g_qkv + (size_t)(0 + bh) * (SS * HD);
    const float* kp = g_qkv + (size_t)(32 + bh) * (SS * HD);
    const float* vp = g_qkv + (size_t)(64 + bh) * (SS * HD);

    // stage Q (tf32), [q][d] stride SQ
    int srow = tid >> 4;
    int sc4  = (tid & 15) * 4;
#pragma unroll
    for (int i = 0; i < 8; i++) {
        int row = srow + i * 16;
        float4 v = *(const float4*)(qp + (size_t)(m0 + row) * HD + sc4);
        *(uint4*)&Qs[row * SQ + sc4] = make_uint4(f2tf(v.x), f2tf(v.y), f2tf(v.z), f2tf(v.w));
    }

    float m0s = -1e30f, m1s = -1e30f;
    float l0 = 0.f, l1 = 0.f;
    float4 oacc[8];
#pragma unroll
    for (int jd = 0; jd < 8; jd++) oacc[jd] = make_float4(0.f, 0.f, 0.f, 0.f);

    for (int kv = 0; kv < SS; kv += 128) {
        __syncthreads();  // prior PV reads done (and Q staged, iter 0)
#pragma unroll
        for (int i = 0; i < 8; i++) {
            int row = srow + i * 16;
            float4 kvec = *(const float4*)(kp + (size_t)(kv + row) * HD + sc4);
            *(uint4*)&KP[row * SKP + sc4] =
                make_uint4(f2tf(kvec.x), f2tf(kvec.y), f2tf(kvec.z), f2tf(kvec.w));
            float4 vvec = *(const float4*)(vp + (size_t)(kv + row) * HD + sc4);
            *(uint4*)&Vs[row * SV + sc4] =
                make_uint4(f2tf(vvec.x), f2tf(vvec.y), f2tf(vvec.z), f2tf(vvec.w));
        }
        __syncthreads();

        // S = Q K^T : warp tile m16 x n128, k=64
        float4 sc[16];
#pragma unroll
        for (int jn = 0; jn < 16; jn++) sc[jn] = make_float4(0.f, 0.f, 0.f, 0.f);
#pragma unroll
        for (int kk = 0; kk < 64; kk += 8) {
            uint32_t af[4];
            int r0 = warp * 16 + g;
            af[0] = Qs[r0 * SQ + kk + t];
            af[1] = Qs[(r0 + 8) * SQ + kk + t];
            af[2] = Qs[r0 * SQ + kk + t + 4];
            af[3] = Qs[(r0 + 8) * SQ + kk + t + 4];
#pragma unroll
            for (int jn = 0; jn < 16; jn++) {
                uint32_t bf[2];
                int nr = jn * 8 + g;
                bf[0] = KP[nr * SKP + kk + t];
                bf[1] = KP[nr * SKP + kk + t + 4];
                mma_tf32(sc[jn], af, bf);
            }
        }
        __syncthreads();  // all QK reads of K done before P overwrites KP

        // warp-local online softmax over full 128-col rows
        {
            float rm0 = -1e30f, rm1 = -1e30f;
#pragma unroll
            for (int jn = 0; jn < 16; jn++) {
                sc[jn].x *= 0.125f; sc[jn].y *= 0.125f;
                sc[jn].z *= 0.125f; sc[jn].w *= 0.125f;
                rm0 = fmaxf(rm0, fmaxf(sc[jn].x, sc[jn].y));
                rm1 = fmaxf(rm1, fmaxf(sc[jn].z, sc[jn].w));
            }
            rm0 = fmaxf(rm0, __shfl_xor_sync(0xffffffffu, rm0, 1));
            rm0 = fmaxf(rm0, __shfl_xor_sync(0xffffffffu, rm0, 2));
            rm1 = fmaxf(rm1, __shfl_xor_sync(0xffffffffu, rm1, 1));
            rm1 = fmaxf(rm1, __shfl_xor_sync(0xffffffffu, rm1, 2));
            float nm0 = fmaxf(m0s, rm0), nm1 = fmaxf(m1s, rm1);
            float a0 = __expf(m0s - nm0), a1 = __expf(m1s - nm1);
            m0s = nm0; m1s = nm1;
            float rs0 = 0.f, rs1 = 0.f;
#pragma unroll
            for (int jn = 0; jn < 16; jn++) {
                sc[jn].x = __expf(sc[jn].x - nm0);
                sc[jn].y = __expf(sc[jn].y - nm0);
                sc[jn].z = __expf(sc[jn].z - nm1);
                sc[jn].w = __expf(sc[jn].w - nm1);
                rs0 += sc[jn].x + sc[jn].y;
                rs1 += sc[jn].z + sc[jn].w;
            }
            rs0 += __shfl_xor_sync(0xffffffffu, rs0, 1);
            rs0 += __shfl_xor_sync(0xffffffffu, rs0, 2);
            rs1 += __shfl_xor_sync(0xffffffffu, rs1, 1);
            rs1 += __shfl_xor_sync(0xffffffffu, rs1, 2);
            l0 = l0 * a0 + rs0;
            l1 = l1 * a1 + rs1;
#pragma unroll
            for (int jd = 0; jd < 8; jd++) {
                oacc[jd].x *= a0; oacc[jd].y *= a0;
                oacc[jd].z *= a1; oacc[jd].w *= a1;
            }
            int rlo = warp * 16 + g, rhi = rlo + 8;
#pragma unroll
            for (int jn = 0; jn < 16; jn++) {
                int c = jn * 8 + 2 * t;
                *(uint2*)&KP[rlo * SKP + c] = make_uint2(f2tf(sc[jn].x), f2tf(sc[jn].y));
                *(uint2*)&KP[rhi * SKP + c] = make_uint2(f2tf(sc[jn].z), f2tf(sc[jn].w));
            }
        }
        __syncthreads();

        // O += P V : warp tile m16 x d64, k=128
#pragma unroll
        for (int kk = 0; kk < 128; kk += 8) {
            uint32_t af[4];
            int r0 = warp * 16 + g;
            af[0] = KP[r0 * SKP + kk + t];
            af[1] = KP[(r0 + 8) * SKP + kk + t];
            af[2] = KP[r0 * SKP + kk + t + 4];
            af[3] = KP[(r0 + 8) * SKP + kk + t + 4];
#pragma unroll
            for (int jd = 0; jd < 8; jd++) {
                uint32_t bf[2];
                int nd = jd * 8 + g;
                bf[0] = Vs[(kk + t) * SV + nd];
                bf[1] = Vs[(kk + t + 4) * SV + nd];
                mma_tf32(oacc[jd], af, bf);
            }
        }
    }

    // finalize: ctx[t, h*64 + d]
    int b = bh >> 4, hh = bh & 15;
    float inv0 = 1.0f / l0, inv1 = 1.0f / l1;
    int t0 = b * SS + m0 + warp * 16 + g;
    int t1 = t0 + 8;
#pragma unroll
    for (int jd = 0; jd < 8; jd++) {
        int d = jd * 8 + 2 * t;
        *(float2*)(g_ctx + (size_t)t0 * H + hh * 64 + d) =
            make_float2(oacc[jd].x * inv0, oacc[jd].y * inv0);
        *(float2*)(g_ctx + (size_t)t1 * H + hh * 64 + d) =
            make_float2(oacc[jd].z * inv1, oacc[jd].w * inv1);
    }
}

// ============================================================
extern "C" void kernel_launch(void* const* d_in, const int* in_sizes, int n_in,
                              void* d_out, int out_size) {
    const float* hidden = (const float*)d_in[0];
    const float* gamma  = (const float*)d_in[1];
    const float* beta   = (const float*)d_in[2];
    const float* Wqkv   = (const float*)d_in[3];
    const float* bqkv   = (const float*)d_in[4];
    const float* Wout   = (const float*)d_in[5];
    const float* bout   = (const float*)d_in[6];
    float* out = (float*)d_out;

    ln_kernel<<<T, 256>>>(hidden, gamma, beta);

    dim3 g1(K3 / 128, T / 128);
    gemm_tf32<0><<<g1, 256>>>(Wqkv, bqkv, nullptr, nullptr);

    cudaFuncSetAttribute(attn_kernel, cudaFuncAttributeMaxDynamicSharedMemorySize, ATTN_SMEM_BYTES);
    attn_kernel<<<dim3(SS / 128, BB * NH), 256, ATTN_SMEM_BYTES>>>();

    dim3 g2(H / 128, T / 128);
    gemm_tf32<1><<<g2, 256>>>(Wout, bout, hidden, out);
}

// round 5
// speedup vs baseline: 4.3056x; 1.4821x over previous
#include <cuda_runtime.h>
#include <cstdint>

#define H  1024
#define NH 16
#define HD 64
#define BB 2
#define SS 2048
#define T  (BB * SS)      // 4096 rows
#define K3 (3 * H)        // 3072

// ---- scratch: referenced ONLY from device code (host arg = shadow bug!) ----
__device__ float g_xn[(size_t)T * H];
__device__ float g_qkv[(size_t)3 * BB * NH * SS * HD];      // [3][B][NH][S][HD]
__device__ float g_ctx[(size_t)T * H];

// ============================================================
// helpers: bf16 pack + mma.m16n8k16 bf16
// ============================================================
__device__ __forceinline__ uint32_t bf2(float lo, float hi) {
    uint32_t r;
    asm("cvt.rn.bf16x2.f32 %0, %1, %2;" : "=r"(r) : "f"(hi), "f"(lo));
    return r;
}

__device__ __forceinline__ void mma_bf16(float4& c, const uint32_t a[4], const uint32_t b[2]) {
    asm volatile(
        "mma.sync.aligned.m16n8k16.row.col.f32.bf16.bf16.f32 "
        "{%0,%1,%2,%3}, {%4,%5,%6,%7}, {%8,%9}, {%0,%1,%2,%3};"
        : "+f"(c.x), "+f"(c.y), "+f"(c.z), "+f"(c.w)
        : "r"(a[0]), "r"(a[1]), "r"(a[2]), "r"(a[3]), "r"(b[0]), "r"(b[1]));
}

// ============================================================
// LayerNorm: one block per row, 256 threads, float4
// ============================================================
__global__ __launch_bounds__(256) void ln_kernel(const float* __restrict__ x,
                                                 const float* __restrict__ gamma,
                                                 const float* __restrict__ beta) {
    int row = blockIdx.x;
    int tid = threadIdx.x;
    const float4* xr = (const float4*)(x + (size_t)row * H);
    float4 v = xr[tid];
    float s  = v.x + v.y + v.z + v.w;
    float ss = v.x * v.x + v.y * v.y + v.z * v.z + v.w * v.w;
#pragma unroll
    for (int off = 16; off > 0; off >>= 1) {
        s  += __shfl_xor_sync(0xffffffffu, s, off);
        ss += __shfl_xor_sync(0xffffffffu, ss, off);
    }
    __shared__ float red[16];
    int warp = tid >> 5, lane = tid & 31;
    if (lane == 0) { red[warp] = s; red[8 + warp] = ss; }
    __syncthreads();
    float ts = 0.f, tss = 0.f;
#pragma unroll
    for (int w = 0; w < 8; w++) { ts += red[w]; tss += red[8 + w]; }
    float mu   = ts * (1.0f / H);
    float var  = tss * (1.0f / H) - mu * mu;
    float rstd = rsqrtf(var + 1e-5f);
    float4 g  = ((const float4*)gamma)[tid];
    float4 bt = ((const float4*)beta)[tid];
    float4 o;
    o.x = (v.x - mu) * rstd * g.x + bt.x;
    o.y = (v.y - mu) * rstd * g.y + bt.y;
    o.z = (v.z - mu) * rstd * g.z + bt.z;
    o.w = (v.w - mu) * rstd * g.w + bt.w;
    ((float4*)(g_xn + (size_t)row * H))[tid] = o;
}

// ============================================================
// BF16 tensor-core GEMM: 128x128 tile, BK=64, 256 threads (8 warps 2x4)
// smem tiles stored as bf16x2 words, row stride 36 words (==4 mod 32).
// MODE 0: A=g_xn, qkv epilogue.  MODE 1: A=g_ctx, out epilogue.
// ============================================================
#define SGA 36

template <int MODE>
__global__ __launch_bounds__(256, 2) void gemm_bf16(const float* __restrict__ Bg,
                                                    const float* __restrict__ bias,
                                                    const float* __restrict__ resid,
                                                    float* __restrict__ outp) {
    __shared__ uint32_t As[128 * SGA];
    __shared__ uint32_t Bs[128 * SGA];
    const float* Ag = (MODE == 0) ? g_xn : g_ctx;   // device-side symbol resolution
    const int Kdim = H;
    int tid = threadIdx.x;
    int lane = tid & 31;
    int warp = tid >> 5;
    int wm = warp >> 2;
    int wn = warp & 3;
    int g = lane >> 2;
    int t = lane & 3;
    int m0 = blockIdx.y * 128;
    int n0 = blockIdx.x * 128;

    float4 acc[4][4];
#pragma unroll
    for (int i = 0; i < 4; i++)
#pragma unroll
        for (int j = 0; j < 4; j++) acc[i][j] = make_float4(0.f, 0.f, 0.f, 0.f);

    int srow = tid >> 4;             // with f = tid + i*256: row = f>>4
    int sc4  = (tid & 15) * 4;       // float col 0..60

    for (int k0 = 0; k0 < Kdim; k0 += 64) {
#pragma unroll
        for (int i = 0; i < 8; i++) {
            int row = srow + i * 16;
            float4 a = *(const float4*)(Ag + (size_t)(m0 + row) * Kdim + k0 + sc4);
            *(uint2*)&As[row * SGA + (sc4 >> 1)] = make_uint2(bf2(a.x, a.y), bf2(a.z, a.w));
            float4 b = *(const float4*)(Bg + (size_t)(n0 + row) * Kdim + k0 + sc4);
            *(uint2*)&Bs[row * SGA + (sc4 >> 1)] = make_uint2(bf2(b.x, b.y), bf2(b.z, b.w));
        }
        __syncthreads();

#pragma unroll
        for (int kw = 0; kw < 32; kw += 8) {   // word offset per k16 step
            uint32_t af[4][4], bf[4][2];
#pragma unroll
            for (int im = 0; im < 4; im++) {
                int r0 = wm * 64 + im * 16 + g;
                af[im][0] = As[r0 * SGA + kw + t];
                af[im][1] = As[(r0 + 8) * SGA + kw + t];
                af[im][2] = As[r0 * SGA + kw + t + 4];
                af[im][3] = As[(r0 + 8) * SGA + kw + t + 4];
            }
#pragma unroll
            for (int jn = 0; jn < 4; jn++) {
                int nr = wn * 32 + jn * 8 + g;
                bf[jn][0] = Bs[nr * SGA + kw + t];
                bf[jn][1] = Bs[nr * SGA + kw + t + 4];
            }
#pragma unroll
            for (int im = 0; im < 4; im++)
#pragma unroll
                for (int jn = 0; jn < 4; jn++)
                    mma_bf16(acc[im][jn], af[im], bf[jn]);
        }
        __syncthreads();
    }

    // epilogue
#pragma unroll
    for (int im = 0; im < 4; im++) {
        int rlo = m0 + wm * 64 + im * 16 + g;
        int rhi = rlo + 8;
#pragma unroll
        for (int jn = 0; jn < 4; jn++) {
            int n = n0 + wn * 32 + jn * 8 + 2 * t;
            float b0 = bias[n], b1 = bias[n + 1];
            if (MODE == 0) {
                int c = n >> 10;
                int rem = n & 1023;
                int hh = rem >> 6;
                int d = rem & 63;
#pragma unroll
                for (int h = 0; h < 2; h++) {
                    int m = h ? rhi : rlo;
                    int bb = m >> 11;
                    int sIdx = m & 2047;
                    float2 r;
                    r.x = (h ? acc[im][jn].z : acc[im][jn].x) + b0;
                    r.y = (h ? acc[im][jn].w : acc[im][jn].y) + b1;
                    float* dst = g_qkv + ((((size_t)(c * 2 + bb) * NH + hh) * SS + sIdx) * HD + d);
                    *(float2*)dst = r;
                }
            } else {
#pragma unroll
                for (int h = 0; h < 2; h++) {
                    int m = h ? rhi : rlo;
                    size_t idx = (size_t)m * H + n;
                    float2 hv = *(const float2*)(resid + idx);
                    float2 r;
                    r.x = (h ? acc[im][jn].z : acc[im][jn].x) + b0 + hv.x;
                    r.y = (h ? acc[im][jn].w : acc[im][jn].y) + b1 + hv.y;
                    *(float2*)(outp + idx) = r;
                }
            }
        }
    }
}

// ============================================================
// Flash attention, bf16 mma, row-complete warp tiling.
// smem (bf16x2 words):
//   Qs [128 rows][36]   (Q, d-words, stride 36 == 4 mod 32)
//   KP [128 rows][68]   (K tile then P tile; stride 68 == 4 mod 32)
//   Vt [64 d-rows][68]  (V TRANSPOSED: word j packs V[2j][d],V[2j+1][d])
// All fragment loads conflict-free; P readback is same-thread.
// ============================================================
#define SQW 36
#define SKPW 68
#define SVW 68
#define QW_OFF 0
#define KPW_OFF (128 * SQW)
#define VW_OFF (KPW_OFF + 128 * SKPW)
#define ATTN_SMEM_WORDS (VW_OFF + 64 * SVW)
#define ATTN_SMEM_BYTES (ATTN_SMEM_WORDS * 4)

__global__ __launch_bounds__(256, 1) void attn_kernel() {
    extern __shared__ uint32_t sm[];
    uint32_t* Qs = sm + QW_OFF;
    uint32_t* KP = sm + KPW_OFF;
    uint32_t* Vt = sm + VW_OFF;

    int tid = threadIdx.x;
    int lane = tid & 31;
    int warp = tid >> 5;     // owns q-rows [warp*16, warp*16+16)
    int g = lane >> 2;
    int t = lane & 3;
    int bh = blockIdx.y;
    int m0 = blockIdx.x * 128;

    const float* qp = g_qkv + (size_t)(0 + bh) * (SS * HD);
    const float* kp = g_qkv + (size_t)(32 + bh) * (SS * HD);
    const float* vp = g_qkv + (size_t)(64 + bh) * (SS * HD);

    // stage Q (bf16 words)
    int srow = tid >> 4;
    int sc4  = (tid & 15) * 4;
#pragma unroll
    for (int i = 0; i < 8; i++) {
        int row = srow + i * 16;
        float4 v = *(const float4*)(qp + (size_t)(m0 + row) * HD + sc4);
        *(uint2*)&Qs[row * SQW + (sc4 >> 1)] = make_uint2(bf2(v.x, v.y), bf2(v.z, v.w));
    }

    // V^T staging coords
    int vj = tid & 63;           // s-pair index 0..63
    int vdg = tid >> 6;          // 0..3 -> d base vdg*16

    float m0s = -1e30f, m1s = -1e30f;
    float l0 = 0.f, l1 = 0.f;
    float4 oacc[8];
#pragma unroll
    for (int jd = 0; jd < 8; jd++) oacc[jd] = make_float4(0.f, 0.f, 0.f, 0.f);

    for (int kv = 0; kv < SS; kv += 128) {
        __syncthreads();  // prior PV reads of KP/Vt done (and Q staged, iter 0)
        // stage K rows (stride 68)
#pragma unroll
        for (int i = 0; i < 8; i++) {
            int row = srow + i * 16;
            float4 kvec = *(const float4*)(kp + (size_t)(kv + row) * HD + sc4);
            *(uint2*)&KP[row * SKPW + (sc4 >> 1)] =
                make_uint2(bf2(kvec.x, kvec.y), bf2(kvec.z, kvec.w));
        }
        // stage V transposed: Vt[d][j] = (V[kv+2j][d], V[kv+2j+1][d])
        {
            const float* v0p = vp + (size_t)(kv + 2 * vj) * HD;
            const float* v1p = v0p + HD;
#pragma unroll
            for (int di = 0; di < 4; di++) {
                int d4 = vdg * 16 + di * 4;
                float4 v0 = *(const float4*)(v0p + d4);
                float4 v1 = *(const float4*)(v1p + d4);
                Vt[(d4 + 0) * SVW + vj] = bf2(v0.x, v1.x);
                Vt[(d4 + 1) * SVW + vj] = bf2(v0.y, v1.y);
                Vt[(d4 + 2) * SVW + vj] = bf2(v0.z, v1.z);
                Vt[(d4 + 3) * SVW + vj] = bf2(v0.w, v1.w);
            }
        }
        __syncthreads();

        // S = Q K^T : warp tile m16 x n128, k=64 (4 k16 steps)
        float4 sc[16];
#pragma unroll
        for (int jn = 0; jn < 16; jn++) sc[jn] = make_float4(0.f, 0.f, 0.f, 0.f);
#pragma unroll
        for (int kw = 0; kw < 32; kw += 8) {
            uint32_t af[4];
            int r0 = warp * 16 + g;
            af[0] = Qs[r0 * SQW + kw + t];
            af[1] = Qs[(r0 + 8) * SQW + kw + t];
            af[2] = Qs[r0 * SQW + kw + t + 4];
            af[3] = Qs[(r0 + 8) * SQW + kw + t + 4];
#pragma unroll
            for (int jn = 0; jn < 16; jn++) {
                uint32_t bf[2];
                int nr = jn * 8 + g;
                bf[0] = KP[nr * SKPW + kw + t];
                bf[1] = KP[nr * SKPW + kw + t + 4];
                mma_bf16(sc[jn], af, bf);
            }
        }
        __syncthreads();  // all QK reads of K done before P overwrites KP

        // warp-local online softmax over full 128-col rows
        {
            float rm0 = -1e30f, rm1 = -1e30f;
#pragma unroll
            for (int jn = 0; jn < 16; jn++) {
                sc[jn].x *= 0.125f; sc[jn].y *= 0.125f;
                sc[jn].z *= 0.125f; sc[jn].w *= 0.125f;
                rm0 = fmaxf(rm0, fmaxf(sc[jn].x, sc[jn].y));
                rm1 = fmaxf(rm1, fmaxf(sc[jn].z, sc[jn].w));
            }
            rm0 = fmaxf(rm0, __shfl_xor_sync(0xffffffffu, rm0, 1));
            rm0 = fmaxf(rm0, __shfl_xor_sync(0xffffffffu, rm0, 2));
            rm1 = fmaxf(rm1, __shfl_xor_sync(0xffffffffu, rm1, 1));
            rm1 = fmaxf(rm1, __shfl_xor_sync(0xffffffffu, rm1, 2));
            float nm0 = fmaxf(m0s, rm0), nm1 = fmaxf(m1s, rm1);
            float a0 = __expf(m0s - nm0), a1 = __expf(m1s - nm1);
            m0s = nm0; m1s = nm1;
            float rs0 = 0.f, rs1 = 0.f;
#pragma unroll
            for (int jn = 0; jn < 16; jn++) {
                sc[jn].x = __expf(sc[jn].x - nm0);
                sc[jn].y = __expf(sc[jn].y - nm0);
                sc[jn].z = __expf(sc[jn].z - nm1);
                sc[jn].w = __expf(sc[jn].w - nm1);
                rs0 += sc[jn].x + sc[jn].y;
                rs1 += sc[jn].z + sc[jn].w;
            }
            rs0 += __shfl_xor_sync(0xffffffffu, rs0, 1);
            rs0 += __shfl_xor_sync(0xffffffffu, rs0, 2);
            rs1 += __shfl_xor_sync(0xffffffffu, rs1, 1);
            rs1 += __shfl_xor_sync(0xffffffffu, rs1, 2);
            l0 = l0 * a0 + rs0;
            l1 = l1 * a1 + rs1;
#pragma unroll
            for (int jd = 0; jd < 8; jd++) {
                oacc[jd].x *= a0; oacc[jd].y *= a0;
                oacc[jd].z *= a1; oacc[jd].w *= a1;
            }
            // store P (bf16x2 words): row r, word jn*4+t
            int rlo = warp * 16 + g, rhi = rlo + 8;
#pragma unroll
            for (int jn = 0; jn < 16; jn++) {
                KP[rlo * SKPW + jn * 4 + t] = bf2(sc[jn].x, sc[jn].y);
                KP[rhi * SKPW + jn * 4 + t] = bf2(sc[jn].z, sc[jn].w);
            }
        }
        // NO barrier: every P word read below was written by the same thread.

        // O += P V : warp tile m16 x d64, k=128 keys (8 k16 steps)
#pragma unroll
        for (int kw = 0; kw < 64; kw += 8) {
            uint32_t af[4];
            int r0 = warp * 16 + g;
            af[0] = KP[r0 * SKPW + kw + t];
            af[1] = KP[(r0 + 8) * SKPW + kw + t];
            af[2] = KP[r0 * SKPW + kw + t + 4];
            af[3] = KP[(r0 + 8) * SKPW + kw + t + 4];
#pragma unroll
            for (int jd = 0; jd < 8; jd++) {
                uint32_t bf[2];
                int nd = jd * 8 + g;
                bf[0] = Vt[nd * SVW + kw + t];
                bf[1] = Vt[nd * SVW + kw + t + 4];
                mma_bf16(oacc[jd], af, bf);
            }
        }
    }

    // finalize: ctx[t, h*64 + d]
    int b = bh >> 4, hh = bh & 15;
    float inv0 = 1.0f / l0, inv1 = 1.0f / l1;
    int t0 = b * SS + m0 + warp * 16 + g;
    int t1 = t0 + 8;
#pragma unroll
    for (int jd = 0; jd < 8; jd++) {
        int d = jd * 8 + 2 * t;
        *(float2*)(g_ctx + (size_t)t0 * H + hh * 64 + d) =
            make_float2(oacc[jd].x * inv0, oacc[jd].y * inv0);
        *(float2*)(g_ctx + (size_t)t1 * H + hh * 64 + d) =
            make_float2(oacc[jd].z * inv1, oacc[jd].w * inv1);
    }
}

// ============================================================
extern "C" void kernel_launch(void* const* d_in, const int* in_sizes, int n_in,
                              void* d_out, int out_size) {
    const float* hidden = (const float*)d_in[0];
    const float* gamma  = (const float*)d_in[1];
    const float* beta   = (const float*)d_in[2];
    const float* Wqkv   = (const float*)d_in[3];
    const float* bqkv   = (const float*)d_in[4];
    const float* Wout   = (const float*)d_in[5];
    const float* bout   = (const float*)d_in[6];
    float* out = (float*)d_out;

    ln_kernel<<<T, 256>>>(hidden, gamma, beta);

    dim3 g1(K3 / 128, T / 128);
    gemm_bf16<0><<<g1, 256>>>(Wqkv, bqkv, nullptr, nullptr);

    cudaFuncSetAttribute(attn_kernel, cudaFuncAttributeMaxDynamicSharedMemorySize, ATTN_SMEM_BYTES);
    attn_kernel<<<dim3(SS / 128, BB * NH), 256, ATTN_SMEM_BYTES>>>();

    dim3 g2(H / 128, T / 128);
    gemm_bf16<1><<<g2, 256>>>(Wout, bout, hidden, out);
}